// round 1
// baseline (speedup 1.0000x reference)
#include <cuda_runtime.h>

#define Bn 64
#define Dd 32
#define Hh 48
#define Ww 48
#define NA (Dd*Hh*Ww)        /* 73728 anchors per batch */
#define TOPK 60
#define NMS_TOPK 20
#define THRESH 0.15f
#define NMS_T 0.05f
#define NBINS 8192
#define CAND_MAX 4096
#define NT 512

__device__ __forceinline__ unsigned fkey(float f) {
    unsigned u = __float_as_uint(f);
    return u ^ ((u & 0x80000000u) ? 0xFFFFFFFFu : 0x80000000u);
}
__device__ __forceinline__ float finv(unsigned k) {
    unsigned u = (k & 0x80000000u) ? (k ^ 0x80000000u) : ~k;
    return __uint_as_float(u);
}

__global__ __launch_bounds__(NT)
void detpost_kernel(const float* __restrict__ Cls,
                    const float* __restrict__ Shp,
                    const float* __restrict__ Off,
                    float* __restrict__ out)
{
    const int b   = blockIdx.x;
    const int tid = threadIdx.x;

    __shared__ union UU {
        unsigned hist[NBINS];
        unsigned long long cand[CAND_MAX];
    } u;
    __shared__ int partial[NT];
    __shared__ int thr_bin;
    __shared__ int cand_cnt;
    __shared__ float s_score[TOPK];
    __shared__ float s_ctr[TOPK][3];
    __shared__ float s_ext[TOPK][3];
    __shared__ unsigned char s_valid[TOPK];
    __shared__ unsigned long long s_mask[TOPK];
    __shared__ unsigned long long s_keep;

    const float*  cls = Cls + (size_t)b * NA;
    const float4* c4  = (const float4*)cls;

    // ---- init ----
    for (int i = tid; i < NBINS; i += NT) u.hist[i] = 0u;
    if (tid == 0) { thr_bin = 0; cand_cnt = 0; }
    __syncthreads();

    // ---- pass 1: 13-bit histogram of monotone keys (warp-aggregated atomics) ----
    // NA/4 = 18432, divisible by NT -> all warps fully active every iteration.
    for (int i = tid; i < NA / 4; i += NT) {
        float4 v = c4[i];
        #pragma unroll
        for (int k = 0; k < 4; k++) {
            float f = (k == 0) ? v.x : (k == 1) ? v.y : (k == 2) ? v.z : v.w;
            int bin = (int)(fkey(f) >> 19);
            unsigned m = __match_any_sync(0xFFFFFFFFu, bin);
            if ((int)(tid & 31) == (__ffs(m) - 1))
                atomicAdd(&u.hist[bin], (unsigned)__popc(m));
        }
    }
    __syncthreads();

    // ---- find threshold bin: largest b with sum_{j>=b} hist[j] >= TOPK ----
    const int BPT = NBINS / NT;               // 16 bins per thread
    int base = tid * BPT;
    int loc = 0;
    #pragma unroll
    for (int j = 0; j < BPT; j++) loc += (int)u.hist[base + j];
    partial[tid] = loc;
    __syncthreads();
    if (tid == 0) {                           // suffix sums (512 iters, cheap)
        int run = 0;
        for (int t = NT - 1; t >= 0; t--) { int p = partial[t]; partial[t] = run; run += p; }
    }
    __syncthreads();
    {
        int cum_above = partial[tid];         // count in bins above this thread's range
        if (cum_above < TOPK && cum_above + loc >= TOPK) {
            int cum = cum_above;
            for (int j = BPT - 1; j >= 0; j--) {
                cum += (int)u.hist[base + j];
                if (cum >= TOPK) { thr_bin = base + j; break; }
            }
        }
    }
    __syncthreads();
    const unsigned klow = (unsigned)thr_bin << 19;
    __syncthreads();   // all done reading hist before reuse as cand[]

    // ---- pass 2: compact candidates (L2-resident re-read) ----
    for (int i = tid; i < NA / 4; i += NT) {
        float4 v = c4[i];
        #pragma unroll
        for (int k = 0; k < 4; k++) {
            float f = (k == 0) ? v.x : (k == 1) ? v.y : (k == 2) ? v.z : v.w;
            unsigned key = fkey(f);
            if (key >= klow) {
                int pos = atomicAdd(&cand_cnt, 1);
                if (pos < CAND_MAX) {
                    unsigned idx = (unsigned)(i * 4 + k);
                    u.cand[pos] = ((unsigned long long)key << 32) | (unsigned)(~idx);
                }
            }
        }
    }
    __syncthreads();
    const int c = min(cand_cnt, CAND_MAX);

    // ---- exact top-60 by rank (keys are unique: idx embedded) ----
    for (int i = tid; i < c; i += NT) {
        unsigned long long ki = u.cand[i];
        int rank = 0;
        for (int j = 0; j < c; j++) rank += (u.cand[j] > ki) ? 1 : 0;
        if (rank < TOPK) {
            unsigned key = (unsigned)(ki >> 32);
            unsigned idx = ~(unsigned)(ki & 0xFFFFFFFFull);
            float raw = finv(key);
            float sc  = 1.0f / (1.0f + expf(-raw));
            s_score[rank] = sc;
            s_valid[rank] = (sc > THRESH) ? 1 : 0;
            int z   = (int)idx / (Hh * Ww);
            int rem = (int)idx % (Hh * Ww);
            int y   = rem / Ww;
            int x   = rem % Ww;
            float a0 = (float)z, a1 = (float)y, a2 = (float)x;
            size_t base3 = (size_t)b * 3 * NA + idx;
            float o0 = Off[base3], o1 = Off[base3 + NA], o2 = Off[base3 + 2 * NA];
            float h0 = Shp[base3], h1 = Shp[base3 + NA], h2 = Shp[base3 + 2 * NA];
            s_ctr[rank][0] = (a0 + o0) * 2.0f;   // stride = (2,2,2)
            s_ctr[rank][1] = (a1 + o1) * 2.0f;
            s_ctr[rank][2] = (a2 + o2) * 2.0f;
            s_ext[rank][0] = 2.0f * h0;
            s_ext[rank][1] = 2.0f * h1;
            s_ext[rank][2] = 2.0f * h2;
        }
    }
    __syncthreads();

    // ---- IoU > NMS_T bitmask, one row per thread ----
    if (tid < TOPK) {
        float ci0 = s_ctr[tid][0], ci1 = s_ctr[tid][1], ci2 = s_ctr[tid][2];
        float ei0 = s_ext[tid][0], ei1 = s_ext[tid][1], ei2 = s_ext[tid][2];
        float li0 = ci0 - 0.5f * ei0, li1 = ci1 - 0.5f * ei1, li2 = ci2 - 0.5f * ei2;
        float hi0 = ci0 + 0.5f * ei0, hi1 = ci1 + 0.5f * ei1, hi2 = ci2 + 0.5f * ei2;
        float vi  = ei0 * ei1 * ei2;
        unsigned long long m = 0ull;
        for (int j = 0; j < TOPK; j++) {
            float ej0 = s_ext[j][0], ej1 = s_ext[j][1], ej2 = s_ext[j][2];
            float lj0 = s_ctr[j][0] - 0.5f * ej0;
            float lj1 = s_ctr[j][1] - 0.5f * ej1;
            float lj2 = s_ctr[j][2] - 0.5f * ej2;
            float hj0 = s_ctr[j][0] + 0.5f * ej0;
            float hj1 = s_ctr[j][1] + 0.5f * ej1;
            float hj2 = s_ctr[j][2] + 0.5f * ej2;
            float d0 = fminf(hi0, hj0) - fmaxf(li0, lj0);
            float d1 = fminf(hi1, hj1) - fmaxf(li1, lj1);
            float d2 = fminf(hi2, hj2) - fmaxf(li2, lj2);
            float inter = fmaxf(d0, 0.0f) * fmaxf(d1, 0.0f) * fmaxf(d2, 0.0f);
            float vj  = ej0 * ej1 * ej2;
            float un  = vi + vj - inter;
            float iou = inter / fmaxf(un, 1e-8f);
            if (iou > NMS_T) m |= (1ull << j);
        }
        s_mask[tid] = m;
    }
    __syncthreads();

    // ---- greedy NMS (serial, but trivial on a u64 mask) ----
    if (tid == 0) {
        unsigned long long km = 0ull;
        for (int i = 0; i < TOPK; i++)
            if (s_valid[i] && !(s_mask[i] & km)) km |= (1ull << i);
        s_keep = km;
    }
    __syncthreads();

    // ---- write output: fill -1, then kept rows at their rank ----
    float* ob = out + (size_t)b * TOPK * 8;
    for (int i = tid; i < TOPK * 8; i += NT) ob[i] = -1.0f;
    __syncthreads();
    if (tid < TOPK) {
        unsigned long long km = s_keep;
        if ((km >> tid) & 1ull) {
            int rank = __popcll(km & ((1ull << tid) - 1ull));
            if (rank < NMS_TOPK) {
                float* row = ob + (size_t)rank * 8;
                row[0] = 1.0f;
                row[1] = s_score[tid];
                row[2] = s_ctr[tid][0];
                row[3] = s_ctr[tid][1];
                row[4] = s_ctr[tid][2];
                row[5] = s_ext[tid][0];
                row[6] = s_ext[tid][1];
                row[7] = s_ext[tid][2];
            }
        }
    }
}

extern "C" void kernel_launch(void* const* d_in, const int* in_sizes, int n_in,
                              void* d_out, int out_size)
{
    const float* Cls = (const float*)d_in[0];
    const float* Shp = (const float*)d_in[1];
    const float* Off = (const float*)d_in[2];
    float* out = (float*)d_out;
    detpost_kernel<<<Bn, NT>>>(Cls, Shp, Off, out);
}

// round 2
// speedup vs baseline: 1.9455x; 1.9455x over previous
#include <cuda_runtime.h>

#define Bn 64
#define Dd 32
#define Hh 48
#define Ww 48
#define NA (Dd*Hh*Ww)        /* 73728 anchors per batch */
#define TOPK 60
#define NMS_TOPK 20
#define THRESH 0.15f
#define NMS_T 0.05f
#define NBINS 8192
#define CAND_MAX 2048
#define NT 512
#define S_SLICES 18
#define NTA 256
#define F4_PER_SLICE ((NA/4)/S_SLICES)   /* 18432/18 = 1024 */
#define T_RAW 2.5f

__device__ unsigned long long g_cand[Bn][CAND_MAX];
__device__ int g_cnt[Bn];

__device__ __forceinline__ unsigned fkey(float f) {
    unsigned u = __float_as_uint(f);
    return u ^ ((u & 0x80000000u) ? 0xFFFFFFFFu : 0x80000000u);
}
__device__ __forceinline__ float finv(unsigned k) {
    unsigned u = (k & 0x80000000u) ? (k ^ 0x80000000u) : ~k;
    return __uint_as_float(u);
}

// ---------------- kernel 0: zero per-batch counters ----------------
__global__ void kzero() {
    if (threadIdx.x < Bn) g_cnt[threadIdx.x] = 0;
}

// ---------------- kernel 1: one-pass gated compaction ----------------
__global__ __launch_bounds__(NTA)
void kcompact(const float* __restrict__ Cls)
{
    const int slice = blockIdx.x;
    const int b     = blockIdx.y;
    const int tid   = threadIdx.x;
    const int lane  = tid & 31;
    const float4* c4 = (const float4*)(Cls + (size_t)b * NA);
    const int base = slice * F4_PER_SLICE;

    #pragma unroll
    for (int it = 0; it < F4_PER_SLICE / NTA; it++) {   // 4 iterations
        int i = base + it * NTA + tid;
        float4 v = c4[i];
        #pragma unroll
        for (int k = 0; k < 4; k++) {
            float f = (k == 0) ? v.x : (k == 1) ? v.y : (k == 2) ? v.z : v.w;
            bool p = (f > T_RAW);
            unsigned ball = __ballot_sync(0xFFFFFFFFu, p);
            if (ball) {
                int leader = __ffs(ball) - 1;
                int pos = 0;
                if (lane == leader) pos = atomicAdd(&g_cnt[b], __popc(ball));
                pos = __shfl_sync(0xFFFFFFFFu, pos, leader);
                if (p) {
                    int off = pos + __popc(ball & ((1u << lane) - 1u));
                    if (off < CAND_MAX) {
                        unsigned idx = (unsigned)(i * 4 + k);
                        g_cand[b][off] =
                            ((unsigned long long)fkey(f) << 32) | (unsigned)(~idx);
                    }
                }
            }
        }
    }
}

// ---------------- kernel 2: per-batch select + NMS + write ----------------
__global__ __launch_bounds__(NT)
void kselect(const float* __restrict__ Cls,
             const float* __restrict__ Shp,
             const float* __restrict__ Off,
             float* __restrict__ out)
{
    const int b   = blockIdx.x;
    const int tid = threadIdx.x;

    __shared__ union UU {
        unsigned hist[NBINS];
        unsigned long long cand[CAND_MAX];
    } u;
    __shared__ int partial[NT];
    __shared__ int thr_bin;
    __shared__ int cand_cnt;
    __shared__ float s_score[TOPK];
    __shared__ float s_ctr[TOPK][3];
    __shared__ float s_ext[TOPK][3];
    __shared__ unsigned char s_valid[TOPK];
    __shared__ unsigned long long s_mask[TOPK];
    __shared__ unsigned long long s_keep;

    const int gc = g_cnt[b];
    const bool fallback = (gc < TOPK) || (gc > CAND_MAX);

    if (!fallback) {
        // -------- fast path: candidates already compacted globally --------
        for (int i = tid; i < gc; i += NT) u.cand[i] = g_cand[b][i];
        if (tid == 0) cand_cnt = gc;
        __syncthreads();
    } else {
        // -------- fallback: exact histogram select (never hit in practice) --------
        const float4* c4 = (const float4*)(Cls + (size_t)b * NA);
        for (int i = tid; i < NBINS; i += NT) u.hist[i] = 0u;
        if (tid == 0) { thr_bin = 0; cand_cnt = 0; }
        __syncthreads();
        for (int i = tid; i < NA / 4; i += NT) {
            float4 v = c4[i];
            #pragma unroll
            for (int k = 0; k < 4; k++) {
                float f = (k == 0) ? v.x : (k == 1) ? v.y : (k == 2) ? v.z : v.w;
                int bin = (int)(fkey(f) >> 19);
                unsigned m = __match_any_sync(0xFFFFFFFFu, bin);
                if ((int)(tid & 31) == (__ffs(m) - 1))
                    atomicAdd(&u.hist[bin], (unsigned)__popc(m));
            }
        }
        __syncthreads();
        const int BPT = NBINS / NT;
        int hbase = tid * BPT;
        int loc = 0;
        #pragma unroll
        for (int j = 0; j < BPT; j++) loc += (int)u.hist[hbase + j];
        partial[tid] = loc;
        __syncthreads();
        if (tid == 0) {
            int run = 0;
            for (int t = NT - 1; t >= 0; t--) { int p = partial[t]; partial[t] = run; run += p; }
        }
        __syncthreads();
        {
            int cum_above = partial[tid];
            if (cum_above < TOPK && cum_above + loc >= TOPK) {
                int cum = cum_above;
                for (int j = BPT - 1; j >= 0; j--) {
                    cum += (int)u.hist[hbase + j];
                    if (cum >= TOPK) { thr_bin = hbase + j; break; }
                }
            }
        }
        __syncthreads();
        const unsigned klow = (unsigned)thr_bin << 19;
        __syncthreads();
        for (int i = tid; i < NA / 4; i += NT) {
            float4 v = c4[i];
            #pragma unroll
            for (int k = 0; k < 4; k++) {
                float f = (k == 0) ? v.x : (k == 1) ? v.y : (k == 2) ? v.z : v.w;
                unsigned key = fkey(f);
                if (key >= klow) {
                    int pos = atomicAdd(&cand_cnt, 1);
                    if (pos < CAND_MAX) {
                        unsigned idx = (unsigned)(i * 4 + k);
                        u.cand[pos] = ((unsigned long long)key << 32) | (unsigned)(~idx);
                    }
                }
            }
        }
        __syncthreads();
    }

    const int c = min(cand_cnt, CAND_MAX);

    // ---- exact top-60 by rank (keys unique: idx embedded) ----
    for (int i = tid; i < c; i += NT) {
        unsigned long long ki = u.cand[i];
        int rank = 0;
        for (int j = 0; j < c; j++) rank += (u.cand[j] > ki) ? 1 : 0;
        if (rank < TOPK) {
            unsigned key = (unsigned)(ki >> 32);
            unsigned idx = ~(unsigned)(ki & 0xFFFFFFFFull);
            float raw = finv(key);
            float sc  = 1.0f / (1.0f + expf(-raw));
            s_score[rank] = sc;
            s_valid[rank] = (sc > THRESH) ? 1 : 0;
            int z   = (int)idx / (Hh * Ww);
            int rem = (int)idx % (Hh * Ww);
            int y   = rem / Ww;
            int x   = rem % Ww;
            size_t base3 = (size_t)b * 3 * NA + idx;
            float o0 = Off[base3], o1 = Off[base3 + NA], o2 = Off[base3 + 2 * NA];
            float h0 = Shp[base3], h1 = Shp[base3 + NA], h2 = Shp[base3 + 2 * NA];
            s_ctr[rank][0] = ((float)z + o0) * 2.0f;   // stride = (2,2,2)
            s_ctr[rank][1] = ((float)y + o1) * 2.0f;
            s_ctr[rank][2] = ((float)x + o2) * 2.0f;
            s_ext[rank][0] = 2.0f * h0;
            s_ext[rank][1] = 2.0f * h1;
            s_ext[rank][2] = 2.0f * h2;
        }
    }
    __syncthreads();

    // ---- IoU > NMS_T bitmask, one row per thread ----
    if (tid < TOPK) {
        float ci0 = s_ctr[tid][0], ci1 = s_ctr[tid][1], ci2 = s_ctr[tid][2];
        float ei0 = s_ext[tid][0], ei1 = s_ext[tid][1], ei2 = s_ext[tid][2];
        float li0 = ci0 - 0.5f * ei0, li1 = ci1 - 0.5f * ei1, li2 = ci2 - 0.5f * ei2;
        float hi0 = ci0 + 0.5f * ei0, hi1 = ci1 + 0.5f * ei1, hi2 = ci2 + 0.5f * ei2;
        float vi  = ei0 * ei1 * ei2;
        unsigned long long m = 0ull;
        for (int j = 0; j < TOPK; j++) {
            float ej0 = s_ext[j][0], ej1 = s_ext[j][1], ej2 = s_ext[j][2];
            float lj0 = s_ctr[j][0] - 0.5f * ej0;
            float lj1 = s_ctr[j][1] - 0.5f * ej1;
            float lj2 = s_ctr[j][2] - 0.5f * ej2;
            float hj0 = s_ctr[j][0] + 0.5f * ej0;
            float hj1 = s_ctr[j][1] + 0.5f * ej1;
            float hj2 = s_ctr[j][2] + 0.5f * ej2;
            float d0 = fminf(hi0, hj0) - fmaxf(li0, lj0);
            float d1 = fminf(hi1, hj1) - fmaxf(li1, lj1);
            float d2 = fminf(hi2, hj2) - fmaxf(li2, lj2);
            float inter = fmaxf(d0, 0.0f) * fmaxf(d1, 0.0f) * fmaxf(d2, 0.0f);
            float vj  = ej0 * ej1 * ej2;
            float un  = vi + vj - inter;
            float iou = inter / fmaxf(un, 1e-8f);
            if (iou > NMS_T) m |= (1ull << j);
        }
        s_mask[tid] = m;
    }
    __syncthreads();

    // ---- greedy NMS on a u64 mask ----
    if (tid == 0) {
        unsigned long long km = 0ull;
        for (int i = 0; i < TOPK; i++)
            if (s_valid[i] && !(s_mask[i] & km)) km |= (1ull << i);
        s_keep = km;
    }
    __syncthreads();

    // ---- write output ----
    float* ob = out + (size_t)b * TOPK * 8;
    for (int i = tid; i < TOPK * 8; i += NT) ob[i] = -1.0f;
    __syncthreads();
    if (tid < TOPK) {
        unsigned long long km = s_keep;
        if ((km >> tid) & 1ull) {
            int rank = __popcll(km & ((1ull << tid) - 1ull));
            if (rank < NMS_TOPK) {
                float* row = ob + (size_t)rank * 8;
                row[0] = 1.0f;
                row[1] = s_score[tid];
                row[2] = s_ctr[tid][0];
                row[3] = s_ctr[tid][1];
                row[4] = s_ctr[tid][2];
                row[5] = s_ext[tid][0];
                row[6] = s_ext[tid][1];
                row[7] = s_ext[tid][2];
            }
        }
    }
}

extern "C" void kernel_launch(void* const* d_in, const int* in_sizes, int n_in,
                              void* d_out, int out_size)
{
    const float* Cls = (const float*)d_in[0];
    const float* Shp = (const float*)d_in[1];
    const float* Off = (const float*)d_in[2];
    float* out = (float*)d_out;

    kzero<<<1, 64>>>();
    dim3 gridA(S_SLICES, Bn);
    kcompact<<<gridA, NTA>>>(Cls);
    kselect<<<Bn, NT>>>(Cls, Shp, Off, out);
}

// round 3
// speedup vs baseline: 2.8504x; 1.4651x over previous
#include <cuda_runtime.h>

#define Bn 64
#define Dd 32
#define Hh 48
#define Ww 48
#define NA (Dd*Hh*Ww)        /* 73728 anchors per batch */
#define TOPK 60
#define NMS_TOPK 20
#define THRESH 0.15f
#define NMS_T 0.05f
#define NBINS 8192
#define NT 256
#define S_SLICES 18
#define SLOT 128
#define CAND_MAX (S_SLICES*SLOT)          /* 2304 */
#define F4_PER_SLICE ((NA/4)/S_SLICES)    /* 1024 */
#define T_RAW 2.8f

__device__ unsigned long long g_scand[Bn][S_SLICES][SLOT];
__device__ int g_scnt[Bn][S_SLICES];
__device__ unsigned g_done[Bn];           /* never reset: old%18==17 marks last arrival */

__device__ __forceinline__ unsigned fkey(float f) {
    unsigned u = __float_as_uint(f);
    return u ^ ((u & 0x80000000u) ? 0xFFFFFFFFu : 0x80000000u);
}
__device__ __forceinline__ float finv(unsigned k) {
    unsigned u = (k & 0x80000000u) ? (k ^ 0x80000000u) : ~k;
    return __uint_as_float(u);
}

__global__ __launch_bounds__(NT)
void detfused(const float* __restrict__ Cls,
              const float* __restrict__ Shp,
              const float* __restrict__ Off,
              float* __restrict__ out)
{
    const int slice = blockIdx.x;
    const int b     = blockIdx.y;
    const int tid   = threadIdx.x;
    const int lane  = tid & 31;

    __shared__ int s_cnt;
    __shared__ unsigned long long s_stage[SLOT];
    __shared__ int s_sel;

    // selector-only storage (allocated in every CTA; only last-CTA uses it)
    __shared__ union UU {
        unsigned hist[NBINS];                 /* 32 KB, fallback only */
        unsigned long long cand[CAND_MAX];    /* 18.4 KB */
    } u;
    __shared__ int partial[NT];
    __shared__ int s_off[S_SLICES + 1];
    __shared__ int s_bad;
    __shared__ int thr_bin;
    __shared__ int cand_cnt;
    __shared__ float s_score[TOPK];
    __shared__ float s_ctr[TOPK][3];
    __shared__ float s_ext[TOPK][3];
    __shared__ unsigned char s_valid[TOPK];
    __shared__ unsigned long long s_mask[TOPK];
    __shared__ unsigned long long s_keep;

    const float4* c4 = (const float4*)(Cls + (size_t)b * NA);

    // ================= phase 1: gated scan of this slice =================
    if (tid == 0) s_cnt = 0;
    __syncthreads();

    #pragma unroll
    for (int it = 0; it < F4_PER_SLICE / NT; it++) {     // 4 iterations
        int gi = slice * F4_PER_SLICE + it * NT + tid;
        float4 v = c4[gi];
        #pragma unroll
        for (int k = 0; k < 4; k++) {
            float f = (k == 0) ? v.x : (k == 1) ? v.y : (k == 2) ? v.z : v.w;
            bool p = (f > T_RAW);
            unsigned ball = __ballot_sync(0xFFFFFFFFu, p);
            if (ball) {
                int leader = __ffs(ball) - 1;
                int pos = 0;
                if (lane == leader) pos = atomicAdd(&s_cnt, __popc(ball));
                pos = __shfl_sync(0xFFFFFFFFu, pos, leader);
                if (p) {
                    int off = pos + __popc(ball & ((1u << lane) - 1u));
                    if (off < SLOT) {
                        unsigned idx = (unsigned)(gi * 4 + k);
                        s_stage[off] =
                            ((unsigned long long)fkey(f) << 32) | (unsigned)(~idx);
                    }
                }
            }
        }
    }
    __syncthreads();

    {
        int cnt = s_cnt;
        if (tid == 0) g_scnt[b][slice] = cnt;            // raw count (overflow detect)
        int w = min(cnt, SLOT);
        if (tid < w) g_scand[b][slice][tid] = s_stage[tid];
    }
    __threadfence();
    __syncthreads();

    if (tid == 0) {
        unsigned old = atomicAdd(&g_done[b], 1u);
        s_sel = ((old % S_SLICES) == (S_SLICES - 1)) ? 1 : 0;
    }
    __syncthreads();
    if (!s_sel) return;
    __threadfence();

    // ================= phase 2 (last CTA of batch b): select + NMS =================
    if (tid == 0) {
        int acc = 0, bad = 0;
        #pragma unroll
        for (int s = 0; s < S_SLICES; s++) {
            int cs = g_scnt[b][s];
            if (cs > SLOT) bad = 1;
            s_off[s] = acc;
            acc += min(cs, SLOT);
        }
        s_off[S_SLICES] = acc;
        cand_cnt = acc;
        s_bad = bad | (acc < TOPK);
    }
    __syncthreads();

    if (!s_bad) {
        // gather compacted candidates from all slices
        for (int s = 0; s < S_SLICES; s++) {
            int base = s_off[s];
            int n = s_off[s + 1] - base;
            if (tid < n) u.cand[base + tid] = g_scand[b][s][tid];
        }
        __syncthreads();
    } else {
        // -------- exact histogram fallback (never hit on this data) --------
        for (int i = tid; i < NBINS; i += NT) u.hist[i] = 0u;
        if (tid == 0) { thr_bin = 0; cand_cnt = 0; }
        __syncthreads();
        for (int i = tid; i < NA / 4; i += NT) {
            float4 v = c4[i];
            #pragma unroll
            for (int k = 0; k < 4; k++) {
                float f = (k == 0) ? v.x : (k == 1) ? v.y : (k == 2) ? v.z : v.w;
                int bin = (int)(fkey(f) >> 19);
                unsigned m = __match_any_sync(0xFFFFFFFFu, bin);
                if (lane == (__ffs(m) - 1))
                    atomicAdd(&u.hist[bin], (unsigned)__popc(m));
            }
        }
        __syncthreads();
        const int BPT = NBINS / NT;                     // 32
        int hbase = tid * BPT;
        int loc = 0;
        #pragma unroll
        for (int j = 0; j < BPT; j++) loc += (int)u.hist[hbase + j];
        partial[tid] = loc;
        __syncthreads();
        if (tid == 0) {
            int run = 0;
            for (int t = NT - 1; t >= 0; t--) { int p = partial[t]; partial[t] = run; run += p; }
        }
        __syncthreads();
        {
            int cum_above = partial[tid];
            if (cum_above < TOPK && cum_above + loc >= TOPK) {
                int cum = cum_above;
                for (int j = BPT - 1; j >= 0; j--) {
                    cum += (int)u.hist[hbase + j];
                    if (cum >= TOPK) { thr_bin = hbase + j; break; }
                }
            }
        }
        __syncthreads();
        const unsigned klow = (unsigned)thr_bin << 19;
        __syncthreads();                                // done with hist before cand reuse
        for (int i = tid; i < NA / 4; i += NT) {
            float4 v = c4[i];
            #pragma unroll
            for (int k = 0; k < 4; k++) {
                float f = (k == 0) ? v.x : (k == 1) ? v.y : (k == 2) ? v.z : v.w;
                unsigned key = fkey(f);
                if (key >= klow) {
                    int pos = atomicAdd(&cand_cnt, 1);
                    if (pos < CAND_MAX) {
                        unsigned idx = (unsigned)(i * 4 + k);
                        u.cand[pos] = ((unsigned long long)key << 32) | (unsigned)(~idx);
                    }
                }
            }
        }
        __syncthreads();
    }

    const int c = min(cand_cnt, CAND_MAX);

    // ---- exact top-60 by rank (keys unique: idx embedded) ----
    for (int i = tid; i < c; i += NT) {
        unsigned long long ki = u.cand[i];
        int rank = 0;
        for (int j = 0; j < c; j++) rank += (u.cand[j] > ki) ? 1 : 0;
        if (rank < TOPK) {
            unsigned key = (unsigned)(ki >> 32);
            unsigned idx = ~(unsigned)(ki & 0xFFFFFFFFull);
            float raw = finv(key);
            float sc  = 1.0f / (1.0f + expf(-raw));
            s_score[rank] = sc;
            s_valid[rank] = (sc > THRESH) ? 1 : 0;
            int z   = (int)idx / (Hh * Ww);
            int rem = (int)idx % (Hh * Ww);
            int y   = rem / Ww;
            int x   = rem % Ww;
            size_t base3 = (size_t)b * 3 * NA + idx;
            float o0 = Off[base3], o1 = Off[base3 + NA], o2 = Off[base3 + 2 * NA];
            float h0 = Shp[base3], h1 = Shp[base3 + NA], h2 = Shp[base3 + 2 * NA];
            s_ctr[rank][0] = ((float)z + o0) * 2.0f;    // stride = (2,2,2)
            s_ctr[rank][1] = ((float)y + o1) * 2.0f;
            s_ctr[rank][2] = ((float)x + o2) * 2.0f;
            s_ext[rank][0] = 2.0f * h0;
            s_ext[rank][1] = 2.0f * h1;
            s_ext[rank][2] = 2.0f * h2;
        }
    }
    __syncthreads();

    // ---- IoU > NMS_T bitmask, one row per thread ----
    if (tid < TOPK) {
        float ci0 = s_ctr[tid][0], ci1 = s_ctr[tid][1], ci2 = s_ctr[tid][2];
        float ei0 = s_ext[tid][0], ei1 = s_ext[tid][1], ei2 = s_ext[tid][2];
        float li0 = ci0 - 0.5f * ei0, li1 = ci1 - 0.5f * ei1, li2 = ci2 - 0.5f * ei2;
        float hi0 = ci0 + 0.5f * ei0, hi1 = ci1 + 0.5f * ei1, hi2 = ci2 + 0.5f * ei2;
        float vi  = ei0 * ei1 * ei2;
        unsigned long long m = 0ull;
        for (int j = 0; j < TOPK; j++) {
            float ej0 = s_ext[j][0], ej1 = s_ext[j][1], ej2 = s_ext[j][2];
            float lj0 = s_ctr[j][0] - 0.5f * ej0;
            float lj1 = s_ctr[j][1] - 0.5f * ej1;
            float lj2 = s_ctr[j][2] - 0.5f * ej2;
            float hj0 = s_ctr[j][0] + 0.5f * ej0;
            float hj1 = s_ctr[j][1] + 0.5f * ej1;
            float hj2 = s_ctr[j][2] + 0.5f * ej2;
            float d0 = fminf(hi0, hj0) - fmaxf(li0, lj0);
            float d1 = fminf(hi1, hj1) - fmaxf(li1, lj1);
            float d2 = fminf(hi2, hj2) - fmaxf(li2, lj2);
            float inter = fmaxf(d0, 0.0f) * fmaxf(d1, 0.0f) * fmaxf(d2, 0.0f);
            float vj  = ej0 * ej1 * ej2;
            float un  = vi + vj - inter;
            float iou = inter / fmaxf(un, 1e-8f);
            if (iou > NMS_T) m |= (1ull << j);
        }
        s_mask[tid] = m;
    }
    __syncthreads();

    // ---- greedy NMS on a u64 mask ----
    if (tid == 0) {
        unsigned long long km = 0ull;
        for (int i = 0; i < TOPK; i++)
            if (s_valid[i] && !(s_mask[i] & km)) km |= (1ull << i);
        s_keep = km;
    }
    __syncthreads();

    // ---- write output: fill -1, then kept rows at their rank ----
    float* ob = out + (size_t)b * TOPK * 8;
    for (int i = tid; i < TOPK * 8; i += NT) ob[i] = -1.0f;
    __syncthreads();
    if (tid < TOPK) {
        unsigned long long km = s_keep;
        if ((km >> tid) & 1ull) {
            int rank = __popcll(km & ((1ull << tid) - 1ull));
            if (rank < NMS_TOPK) {
                float* row = ob + (size_t)rank * 8;
                row[0] = 1.0f;
                row[1] = s_score[tid];
                row[2] = s_ctr[tid][0];
                row[3] = s_ctr[tid][1];
                row[4] = s_ctr[tid][2];
                row[5] = s_ext[tid][0];
                row[6] = s_ext[tid][1];
                row[7] = s_ext[tid][2];
            }
        }
    }
}

extern "C" void kernel_launch(void* const* d_in, const int* in_sizes, int n_in,
                              void* d_out, int out_size)
{
    const float* Cls = (const float*)d_in[0];
    const float* Shp = (const float*)d_in[1];
    const float* Off = (const float*)d_in[2];
    float* out = (float*)d_out;

    dim3 grid(S_SLICES, Bn);
    detfused<<<grid, NT>>>(Cls, Shp, Off, out);
}

// round 4
// speedup vs baseline: 3.0703x; 1.0771x over previous
#include <cuda_runtime.h>

#define Bn 64
#define Dd 32
#define Hh 48
#define Ww 48
#define NA (Dd*Hh*Ww)        /* 73728 anchors per batch */
#define TOPK 60
#define NMS_TOPK 20
#define THRESH 0.15f
#define NMS_T 0.05f
#define NBINS 4096
#define NT 256
#define S_SLICES 18
#define SLOT 128
#define CAND_MAX (S_SLICES*SLOT)          /* 2304 */
#define F4_PER_SLICE ((NA/4)/S_SLICES)    /* 1024 */
#define T_RAW 2.8f

__device__ unsigned long long g_scand[Bn][S_SLICES][SLOT];
__device__ int g_scnt[Bn][S_SLICES];
__device__ unsigned g_done[Bn];           /* never reset: old%18==17 marks last arrival */

__device__ __forceinline__ unsigned fkey(float f) {
    unsigned u = __float_as_uint(f);
    return u ^ ((u & 0x80000000u) ? 0xFFFFFFFFu : 0x80000000u);
}
__device__ __forceinline__ float finv(unsigned k) {
    unsigned u = (k & 0x80000000u) ? (k ^ 0x80000000u) : ~k;
    return __uint_as_float(u);
}

__global__ __launch_bounds__(NT)
void detfused(const float* __restrict__ Cls,
              const float* __restrict__ Shp,
              const float* __restrict__ Off,
              float* __restrict__ out)
{
    const int slice = blockIdx.x;
    const int b     = blockIdx.y;
    const int tid   = threadIdx.x;
    const int lane  = tid & 31;

    __shared__ int s_cnt;
    __shared__ unsigned long long s_stage[SLOT];
    __shared__ int s_sel;

    __shared__ union UU {
        unsigned hist[NBINS];                 /* 16 KB, fallback only */
        unsigned long long cand[CAND_MAX];    /* 18.4 KB */
    } u;
    __shared__ int partial[NT];
    __shared__ int s_off[S_SLICES];
    __shared__ int s_n[S_SLICES];
    __shared__ int s_bad;
    __shared__ int thr_bin;
    __shared__ int cand_cnt;
    __shared__ float s_score[TOPK];
    __shared__ float s_ctr[TOPK][3];
    __shared__ float s_ext[TOPK][3];
    __shared__ unsigned char s_valid[TOPK];
    __shared__ unsigned long long s_mask[TOPK];
    __shared__ unsigned long long s_keep;

    const float4* c4 = (const float4*)(Cls + (size_t)b * NA);

    // ================= phase 1: gated scan of this slice (MLP=4) =================
    if (tid == 0) s_cnt = 0;
    __syncthreads();

    {
        const int base = slice * F4_PER_SLICE + tid;
        float4 v0 = c4[base];
        float4 v1 = c4[base + NT];
        float4 v2 = c4[base + 2 * NT];
        float4 v3 = c4[base + 3 * NT];

        #pragma unroll
        for (int it = 0; it < 4; it++) {
            float4 v = (it == 0) ? v0 : (it == 1) ? v1 : (it == 2) ? v2 : v3;
            int gi = base + it * NT;
            #pragma unroll
            for (int k = 0; k < 4; k++) {
                float f = (k == 0) ? v.x : (k == 1) ? v.y : (k == 2) ? v.z : v.w;
                bool p = (f > T_RAW);
                unsigned ball = __ballot_sync(0xFFFFFFFFu, p);
                if (ball) {
                    int leader = __ffs(ball) - 1;
                    int pos = 0;
                    if (lane == leader) pos = atomicAdd(&s_cnt, __popc(ball));
                    pos = __shfl_sync(0xFFFFFFFFu, pos, leader);
                    if (p) {
                        int off = pos + __popc(ball & ((1u << lane) - 1u));
                        if (off < SLOT) {
                            unsigned idx = (unsigned)(gi * 4 + k);
                            s_stage[off] =
                                ((unsigned long long)fkey(f) << 32) | (unsigned)(~idx);
                        }
                    }
                }
            }
        }
    }
    __syncthreads();

    {
        int cnt = s_cnt;
        if (tid == 0) g_scnt[b][slice] = cnt;            // raw count (overflow detect)
        int w = min(cnt, SLOT);
        if (tid < w) g_scand[b][slice][tid] = s_stage[tid];
    }
    __threadfence();
    __syncthreads();

    if (tid == 0) {
        unsigned old = atomicAdd(&g_done[b], 1u);
        s_sel = ((old % S_SLICES) == (S_SLICES - 1)) ? 1 : 0;
    }
    __syncthreads();
    if (!s_sel) return;
    __threadfence();

    // ================= phase 2 (last CTA of batch b): select + NMS =================
    if (tid == 0) {
        int acc = 0, bad = 0;
        #pragma unroll
        for (int s = 0; s < S_SLICES; s++) {
            int cs = g_scnt[b][s];
            if (cs > SLOT) bad = 1;
            int n = min(cs, SLOT);
            s_off[s] = acc;
            s_n[s]   = n;
            acc += n;
        }
        cand_cnt = acc;
        s_bad = bad | (acc < TOPK);
    }
    __syncthreads();

    if (!s_bad) {
        // flat parallel gather: 9 independent predicated LDGs per thread
        #pragma unroll
        for (int i = tid; i < S_SLICES * SLOT; i += NT) {
            int s = i >> 7;          // /SLOT
            int j = i & (SLOT - 1);  // %SLOT
            if (j < s_n[s]) u.cand[s_off[s] + j] = g_scand[b][s][j];
        }
        __syncthreads();
    } else {
        // -------- exact histogram fallback (never hit on this data) --------
        for (int i = tid; i < NBINS; i += NT) u.hist[i] = 0u;
        if (tid == 0) { thr_bin = 0; cand_cnt = 0; }
        __syncthreads();
        for (int i = tid; i < NA / 4; i += NT) {
            float4 v = c4[i];
            #pragma unroll
            for (int k = 0; k < 4; k++) {
                float f = (k == 0) ? v.x : (k == 1) ? v.y : (k == 2) ? v.z : v.w;
                int bin = (int)(fkey(f) >> 20);
                unsigned m = __match_any_sync(0xFFFFFFFFu, bin);
                if (lane == (__ffs(m) - 1))
                    atomicAdd(&u.hist[bin], (unsigned)__popc(m));
            }
        }
        __syncthreads();
        const int BPT = NBINS / NT;                     // 16
        int hbase = tid * BPT;
        int loc = 0;
        #pragma unroll
        for (int j = 0; j < BPT; j++) loc += (int)u.hist[hbase + j];
        partial[tid] = loc;
        __syncthreads();
        if (tid == 0) {
            int run = 0;
            for (int t = NT - 1; t >= 0; t--) { int p = partial[t]; partial[t] = run; run += p; }
        }
        __syncthreads();
        {
            int cum_above = partial[tid];
            if (cum_above < TOPK && cum_above + loc >= TOPK) {
                int cum = cum_above;
                for (int j = BPT - 1; j >= 0; j--) {
                    cum += (int)u.hist[hbase + j];
                    if (cum >= TOPK) { thr_bin = hbase + j; break; }
                }
            }
        }
        __syncthreads();
        const unsigned klow = (unsigned)thr_bin << 20;
        __syncthreads();                                // done with hist before cand reuse
        for (int i = tid; i < NA / 4; i += NT) {
            float4 v = c4[i];
            #pragma unroll
            for (int k = 0; k < 4; k++) {
                float f = (k == 0) ? v.x : (k == 1) ? v.y : (k == 2) ? v.z : v.w;
                unsigned key = fkey(f);
                if (key >= klow) {
                    int pos = atomicAdd(&cand_cnt, 1);
                    if (pos < CAND_MAX) {
                        unsigned idx = (unsigned)(i * 4 + k);
                        u.cand[pos] = ((unsigned long long)key << 32) | (unsigned)(~idx);
                    }
                }
            }
        }
        __syncthreads();
    }

    const int c = min(cand_cnt, CAND_MAX);

    // ---- exact top-60 by rank (keys unique: idx embedded) ----
    for (int i = tid; i < c; i += NT) {
        unsigned long long ki = u.cand[i];
        int rank = 0;
        for (int j = 0; j < c; j++) rank += (u.cand[j] > ki) ? 1 : 0;
        if (rank < TOPK) {
            unsigned key = (unsigned)(ki >> 32);
            unsigned idx = ~(unsigned)(ki & 0xFFFFFFFFull);
            float raw = finv(key);
            float sc  = 1.0f / (1.0f + expf(-raw));
            s_score[rank] = sc;
            s_valid[rank] = (sc > THRESH) ? 1 : 0;
            int z   = (int)idx / (Hh * Ww);
            int rem = (int)idx % (Hh * Ww);
            int y   = rem / Ww;
            int x   = rem % Ww;
            size_t base3 = (size_t)b * 3 * NA + idx;
            float o0 = Off[base3], o1 = Off[base3 + NA], o2 = Off[base3 + 2 * NA];
            float h0 = Shp[base3], h1 = Shp[base3 + NA], h2 = Shp[base3 + 2 * NA];
            s_ctr[rank][0] = ((float)z + o0) * 2.0f;    // stride = (2,2,2)
            s_ctr[rank][1] = ((float)y + o1) * 2.0f;
            s_ctr[rank][2] = ((float)x + o2) * 2.0f;
            s_ext[rank][0] = 2.0f * h0;
            s_ext[rank][1] = 2.0f * h1;
            s_ext[rank][2] = 2.0f * h2;
        }
    }
    __syncthreads();

    // ---- IoU > NMS_T bitmask, one row per thread ----
    if (tid < TOPK) {
        float ci0 = s_ctr[tid][0], ci1 = s_ctr[tid][1], ci2 = s_ctr[tid][2];
        float ei0 = s_ext[tid][0], ei1 = s_ext[tid][1], ei2 = s_ext[tid][2];
        float li0 = ci0 - 0.5f * ei0, li1 = ci1 - 0.5f * ei1, li2 = ci2 - 0.5f * ei2;
        float hi0 = ci0 + 0.5f * ei0, hi1 = ci1 + 0.5f * ei1, hi2 = ci2 + 0.5f * ei2;
        float vi  = ei0 * ei1 * ei2;
        unsigned long long m = 0ull;
        for (int j = 0; j < TOPK; j++) {
            float ej0 = s_ext[j][0], ej1 = s_ext[j][1], ej2 = s_ext[j][2];
            float lj0 = s_ctr[j][0] - 0.5f * ej0;
            float lj1 = s_ctr[j][1] - 0.5f * ej1;
            float lj2 = s_ctr[j][2] - 0.5f * ej2;
            float hj0 = s_ctr[j][0] + 0.5f * ej0;
            float hj1 = s_ctr[j][1] + 0.5f * ej1;
            float hj2 = s_ctr[j][2] + 0.5f * ej2;
            float d0 = fminf(hi0, hj0) - fmaxf(li0, lj0);
            float d1 = fminf(hi1, hj1) - fmaxf(li1, lj1);
            float d2 = fminf(hi2, hj2) - fmaxf(li2, lj2);
            float inter = fmaxf(d0, 0.0f) * fmaxf(d1, 0.0f) * fmaxf(d2, 0.0f);
            float vj  = ej0 * ej1 * ej2;
            float un  = vi + vj - inter;
            float iou = inter / fmaxf(un, 1e-8f);
            if (iou > NMS_T) m |= (1ull << j);
        }
        s_mask[tid] = m;
    }
    __syncthreads();

    // ---- greedy NMS on a u64 mask ----
    if (tid == 0) {
        unsigned long long km = 0ull;
        for (int i = 0; i < TOPK; i++)
            if (s_valid[i] && !(s_mask[i] & km)) km |= (1ull << i);
        s_keep = km;
    }
    __syncthreads();

    // ---- write output: fill -1, then kept rows at their rank ----
    float* ob = out + (size_t)b * TOPK * 8;
    for (int i = tid; i < TOPK * 8; i += NT) ob[i] = -1.0f;
    __syncthreads();
    if (tid < TOPK) {
        unsigned long long km = s_keep;
        if ((km >> tid) & 1ull) {
            int rank = __popcll(km & ((1ull << tid) - 1ull));
            if (rank < NMS_TOPK) {
                float* row = ob + (size_t)rank * 8;
                row[0] = 1.0f;
                row[1] = s_score[tid];
                row[2] = s_ctr[tid][0];
                row[3] = s_ctr[tid][1];
                row[4] = s_ctr[tid][2];
                row[5] = s_ext[tid][0];
                row[6] = s_ext[tid][1];
                row[7] = s_ext[tid][2];
            }
        }
    }
}

extern "C" void kernel_launch(void* const* d_in, const int* in_sizes, int n_in,
                              void* d_out, int out_size)
{
    const float* Cls = (const float*)d_in[0];
    const float* Shp = (const float*)d_in[1];
    const float* Off = (const float*)d_in[2];
    float* out = (float*)d_out;

    dim3 grid(S_SLICES, Bn);
    detfused<<<grid, NT>>>(Cls, Shp, Off, out);
}